// round 13
// baseline (speedup 1.0000x reference)
#include <cuda_runtime.h>
#include <stdint.h>

// ScaledNeuron: IF neuron, soft reset, V_TH=1.0, SCALE=1.0, v0=0.5.
// xs: [B=16, C=64, H=64, W=64, T=8] fp32, T contiguous.
//
// 256-bit variant: Blackwell (sm_100+) supports ld/st.global.v8.f32.
// One thread = one spatial location = ONE 32-byte load of all 8 timesteps,
// sequential 8-step IF recurrence in registers, ONE 32-byte store.
// Warp-level: each LDG.E.256 / STG.E.256 covers 1 KB fully contiguous.
// No shfl, no divergence, no double-pass ALU.

__global__ __launch_bounds__(256)
void scaled_neuron_kernel(const float* __restrict__ in,
                          float* __restrict__ out,
                          int n_loc) {
    int i = blockIdx.x * blockDim.x + threadIdx.x;
    if (i >= n_loc) return;

    const float* pin = in + 8ll * (long long)i;
    float* pout = out + 8ll * (long long)i;

    float x0, x1, x2, x3, x4, x5, x6, x7;
    asm volatile(
        "ld.global.nc.v8.f32 {%0, %1, %2, %3, %4, %5, %6, %7}, [%8];"
        : "=f"(x0), "=f"(x1), "=f"(x2), "=f"(x3),
          "=f"(x4), "=f"(x5), "=f"(x6), "=f"(x7)
        : "l"(pin));

    float v = 0.5f;
    float s0, s1, s2, s3, s4, s5, s6, s7;
    v += x0; s0 = (v >= 1.0f) ? 1.0f : 0.0f; v -= s0;
    v += x1; s1 = (v >= 1.0f) ? 1.0f : 0.0f; v -= s1;
    v += x2; s2 = (v >= 1.0f) ? 1.0f : 0.0f; v -= s2;
    v += x3; s3 = (v >= 1.0f) ? 1.0f : 0.0f; v -= s3;
    v += x4; s4 = (v >= 1.0f) ? 1.0f : 0.0f; v -= s4;
    v += x5; s5 = (v >= 1.0f) ? 1.0f : 0.0f; v -= s5;
    v += x6; s6 = (v >= 1.0f) ? 1.0f : 0.0f; v -= s6;
    v += x7; s7 = (v >= 1.0f) ? 1.0f : 0.0f; v -= s7;

    asm volatile(
        "st.global.v8.f32 [%0], {%1, %2, %3, %4, %5, %6, %7, %8};"
        :: "l"(pout),
           "f"(s0), "f"(s1), "f"(s2), "f"(s3),
           "f"(s4), "f"(s5), "f"(s6), "f"(s7)
        : "memory");
}

extern "C" void kernel_launch(void* const* d_in, const int* in_sizes, int n_in,
                              void* d_out, int out_size) {
    const float* in = (const float*)d_in[0];
    float* out = (float*)d_out;

    int n_loc = in_sizes[0] / 8;  // 4,194,304 spatial locations
    int threads = 256;
    int blocks = (n_loc + threads - 1) / threads;  // 16384

    scaled_neuron_kernel<<<blocks, threads>>>(in, out, n_loc);
}

// round 14
// speedup vs baseline: 1.0021x; 1.0021x over previous
#include <cuda_runtime.h>
#include <stdint.h>

// ScaledNeuron: IF neuron, soft reset, V_TH=1.0, SCALE=1.0, v0=0.5.
// xs: [B=16, C=64, H=64, W=64, T=8] fp32, T contiguous.
//
// FINAL-candidate: 256-bit accesses (sm_100 ld/st.global.v8.f32) with
// MLP_p1=2. Each thread handles TWO spatial locations, at i and i + half
// (split streams keep every warp instruction covering 1 KB of fully
// contiguous memory). Both v8 loads are front-batched; the two 8-step IF
// recurrences are independent register chains. 268 MB total traffic —
// DRAM-roofline-bound at ~5.95 TB/s steady state.

__device__ __forceinline__ void if8(const float x[8], float s[8]) {
    float v = 0.5f;
#pragma unroll
    for (int t = 0; t < 8; t++) {
        v += x[t];
        float sp = (v >= 1.0f) ? 1.0f : 0.0f;
        v -= sp;
        s[t] = sp;
    }
}

__global__ __launch_bounds__(256)
void scaled_neuron_kernel(const float* __restrict__ in,
                          float* __restrict__ out,
                          int half) {            // half = n_loc / 2
    int i = blockIdx.x * blockDim.x + threadIdx.x;
    if (i >= half) return;

    const float* p0 = in + 8ll * (long long)i;
    const float* p1 = in + 8ll * (long long)(i + half);

    float a[8], b[8];
    // Front-batched 256-bit loads (MLP_p1 = 2), each warp instr = 1 KB burst.
    asm volatile(
        "ld.global.nc.v8.f32 {%0, %1, %2, %3, %4, %5, %6, %7}, [%8];"
        : "=f"(a[0]), "=f"(a[1]), "=f"(a[2]), "=f"(a[3]),
          "=f"(a[4]), "=f"(a[5]), "=f"(a[6]), "=f"(a[7])
        : "l"(p0));
    asm volatile(
        "ld.global.nc.v8.f32 {%0, %1, %2, %3, %4, %5, %6, %7}, [%8];"
        : "=f"(b[0]), "=f"(b[1]), "=f"(b[2]), "=f"(b[3]),
          "=f"(b[4]), "=f"(b[5]), "=f"(b[6]), "=f"(b[7])
        : "l"(p1));

    float sa[8], sb[8];
    if8(a, sa);
    if8(b, sb);

    float* q0 = out + 8ll * (long long)i;
    float* q1 = out + 8ll * (long long)(i + half);
    asm volatile(
        "st.global.v8.f32 [%0], {%1, %2, %3, %4, %5, %6, %7, %8};"
        :: "l"(q0),
           "f"(sa[0]), "f"(sa[1]), "f"(sa[2]), "f"(sa[3]),
           "f"(sa[4]), "f"(sa[5]), "f"(sa[6]), "f"(sa[7])
        : "memory");
    asm volatile(
        "st.global.v8.f32 [%0], {%1, %2, %3, %4, %5, %6, %7, %8};"
        :: "l"(q1),
           "f"(sb[0]), "f"(sb[1]), "f"(sb[2]), "f"(sb[3]),
           "f"(sb[4]), "f"(sb[5]), "f"(sb[6]), "f"(sb[7])
        : "memory");
}

extern "C" void kernel_launch(void* const* d_in, const int* in_sizes, int n_in,
                              void* d_out, int out_size) {
    const float* in = (const float*)d_in[0];
    float* out = (float*)d_out;

    int n_loc = in_sizes[0] / 8;  // 4,194,304 spatial locations
    int half = n_loc / 2;         // 2,097,152
    int threads = 256;
    int blocks = (half + threads - 1) / threads;  // 8192

    scaled_neuron_kernel<<<blocks, threads>>>(in, out, half);
}

// round 17
// speedup vs baseline: 1.0057x; 1.0035x over previous
#include <cuda_runtime.h>
#include <stdint.h>

// ScaledNeuron: IF neuron, soft reset, V_TH=1.0, SCALE=1.0, v0=0.5.
// xs: [B=16, C=64, H=64, W=64, T=8] fp32, T contiguous.
//
// FINAL: DRAM-roofline-bound kernel (268 MB @ ~5.95 TB/s steady state;
// dur_us 45.088 confirmed in two independent benches).
//
// One float4 (= 4 timesteps of half a location) per lane; the 8-step
// temporal recurrence is stitched across the even/odd lane pair with one
// shfl_up. All load/store streams are lane-consecutive (16B/lane ->
// minimal L1 wavefronts). MLP_p1 = 2 front-batched loads per thread
// (i and i + half; half is even so lane parity == element parity for
// both streams). regs=26, occ ~79%.
//
// Even lane 2k: t0..3 of a location; odd lane 2k+1: t4..7 of the SAME
// location:
//   pass 1: all lanes run 4 IF steps from v=0.5 (valid on even lanes)
//   shfl_up(v,1): odd lane receives partner's v after t3
//   pass 2: odd lanes re-run their 4 steps from that v.

__device__ __forceinline__ float4 if4(float4 x, float& v) {
    float s0, s1, s2, s3;
    v += x.x; s0 = (v >= 1.0f) ? 1.0f : 0.0f; v -= s0;
    v += x.y; s1 = (v >= 1.0f) ? 1.0f : 0.0f; v -= s1;
    v += x.z; s2 = (v >= 1.0f) ? 1.0f : 0.0f; v -= s2;
    v += x.w; s3 = (v >= 1.0f) ? 1.0f : 0.0f; v -= s3;
    return make_float4(s0, s1, s2, s3);
}

__global__ __launch_bounds__(256)
void scaled_neuron_kernel(const float4* __restrict__ in,
                          float4* __restrict__ out,
                          int half) {           // half = n4 / 2 (even)
    int i = blockIdx.x * blockDim.x + threadIdx.x;
    if (i >= half) return;

    // Front-batched, both perfectly coalesced (MLP_p1 = 2).
    float4 x0 = in[i];
    float4 x1 = in[i + half];

    // Pass 1 (valid for even lanes: t0..3 of each location).
    float v0 = 0.5f, v1 = 0.5f;
    float4 s0 = if4(x0, v0);
    float4 s1 = if4(x1, v1);

    // Even lane hands its v-after-t3 to its odd partner.
    float p0 = __shfl_up_sync(0xffffffffu, v0, 1);
    float p1 = __shfl_up_sync(0xffffffffu, v1, 1);

    if (threadIdx.x & 1) {
        float w0 = p0, w1 = p1;
        s0 = if4(x0, w0);   // Pass 2: t4..7 from partner's v.
        s1 = if4(x1, w1);
    }

    out[i]        = s0;
    out[i + half] = s1;
}

extern "C" void kernel_launch(void* const* d_in, const int* in_sizes, int n_in,
                              void* d_out, int out_size) {
    const float4* in = (const float4*)d_in[0];
    float4* out = (float4*)d_out;

    int n4 = in_sizes[0] / 4;   // 8,388,608 float4
    int half = n4 / 2;          // 4,194,304 (even)
    int threads = 256;
    int blocks = (half + threads - 1) / threads;  // 16384

    scaled_neuron_kernel<<<blocks, threads>>>(in, out, half);
}